// round 2
// baseline (speedup 1.0000x reference)
#include <cuda_runtime.h>

// Problem constants
#define B 4
#define S 2048
#define D 512
#define H 8
#define A 64
#define BH (B*H)
#define NT (S/64)   // 32 tiles of 64 along sequence

// Scratch (device globals: no allocation allowed)
__device__ float g_q[(size_t)BH*S*A];     // [bh][s][a]
__device__ float g_k[(size_t)BH*S*A];
__device__ float g_v[(size_t)BH*S*A];
__device__ float g_att[(size_t)B*S*(H*A)]; // [b][s][h*a]

// ---------------------------------------------------------------------------
// QKV projection: out[bh][s][a] = X[b][s][:] @ W[h] + bias[h]
// grid = (S/64, B*H, 3), block = 256 (16x16), 4x4 micro-tile per thread
// ---------------------------------------------------------------------------
__global__ __launch_bounds__(256) void proj_kernel(
    const float* __restrict__ q_in, const float* __restrict__ k_in,
    const float* __restrict__ v_in,
    const float* __restrict__ Wq, const float* __restrict__ bq,
    const float* __restrict__ Wk, const float* __restrict__ bk,
    const float* __restrict__ Wv, const float* __restrict__ bv)
{
    __shared__ float Xs[16][68];   // [k][m]
    __shared__ float Ws[16][68];   // [k][n]

    const int which = blockIdx.z;
    const float* X   = (which == 0) ? q_in : (which == 1) ? k_in : v_in;
    const float* W   = (which == 0) ? Wq   : (which == 1) ? Wk   : Wv;
    const float* bias= (which == 0) ? bq   : (which == 1) ? bk   : bv;
    float* out       = (which == 0) ? g_q  : (which == 1) ? g_k  : g_v;

    const int bh = blockIdx.y;
    const int b  = bh >> 3, h = bh & 7;
    const int s0 = blockIdx.x * 64;
    const int tid = threadIdx.x;
    const int ty = tid >> 4, tx = tid & 15;

    const float* Xb = X + ((size_t)(b * S + s0)) * D;
    const float* Wb = W + (size_t)h * D * A;

    float acc[4][4];
    #pragma unroll
    for (int i = 0; i < 4; i++)
        #pragma unroll
        for (int j = 0; j < 4; j++) acc[i][j] = 0.f;

    for (int k0 = 0; k0 < D; k0 += 16) {
        {   // X tile 64x16 -> Xs[k][m]  (256 thr * 4 = 1024 = 64*16)
            int row = tid >> 2;
            int col = (tid & 3) * 4;
            float4 v = *(const float4*)(Xb + (size_t)row * D + k0 + col);
            Xs[col + 0][row] = v.x; Xs[col + 1][row] = v.y;
            Xs[col + 2][row] = v.z; Xs[col + 3][row] = v.w;
        }
        {   // W tile 16x64 -> Ws[k][n]
            int row = tid >> 4;
            int col = (tid & 15) * 4;
            *(float4*)&Ws[row][col] = *(const float4*)(Wb + (size_t)(k0 + row) * A + col);
        }
        __syncthreads();
        #pragma unroll
        for (int kk = 0; kk < 16; kk++) {
            float4 a4 = *(const float4*)&Xs[kk][ty * 4];
            float4 b4 = *(const float4*)&Ws[kk][tx * 4];
            float av[4] = {a4.x, a4.y, a4.z, a4.w};
            float bv4[4] = {b4.x, b4.y, b4.z, b4.w};
            #pragma unroll
            for (int i = 0; i < 4; i++)
                #pragma unroll
                for (int j = 0; j < 4; j++)
                    acc[i][j] = fmaf(av[i], bv4[j], acc[i][j]);
        }
        __syncthreads();
    }
    #pragma unroll
    for (int i = 0; i < 4; i++) {
        int s = s0 + ty * 4 + i;
        #pragma unroll
        for (int j = 0; j < 4; j++) {
            int a = tx * 4 + j;
            out[((size_t)bh * S + s) * A + a] = acc[i][j] + bias[h * A + a];
        }
    }
}

// ---------------------------------------------------------------------------
// Flash-style attention with reverse-causal mask (valid keys are kg > qg).
// grid = (S/64 query tiles, B*H), block = 256 (16x16), 4x4 micro-tiles.
// Each block: query tile [s0, s0+64); iterate key tiles j = qt .. NT-1.
// Diagonal tile applies -1e9 mask; row S-1 fixed up by a separate kernel.
// ---------------------------------------------------------------------------
__global__ __launch_bounds__(256) void attn_kernel()
{
    __shared__ float Qt[64 * 64];    // [dim][qrow]
    __shared__ float KtPs[64 * 64];  // phase 1: Kt [dim][key]; phase 2: P [qrow][key]
    __shared__ float Vs[64 * 64];    // [key][dim]

    const int qt = blockIdx.x;
    const int bh = blockIdx.y;
    const int s0 = qt * 64;
    const int tid = threadIdx.x;
    const int ty = tid >> 4, tx = tid & 15;

    {   // load full Q tile (64x64) transposed: 16 floats per thread
        const float* Qg = g_q + ((size_t)bh * S + s0) * A;
        int r = tid >> 2;
        #pragma unroll
        for (int cc = 0; cc < 4; cc++) {
            int c = (tid & 3) * 4 + cc * 16;
            float4 v = *(const float4*)(Qg + (size_t)r * A + c);
            Qt[(c + 0) * 64 + r] = v.x;
            Qt[(c + 1) * 64 + r] = v.y;
            Qt[(c + 2) * 64 + r] = v.z;
            Qt[(c + 3) * 64 + r] = v.w;
        }
    }

    float m_run[4], l_run[4], acc[4][4];
    #pragma unroll
    for (int i = 0; i < 4; i++) {
        m_run[i] = -1e9f; l_run[i] = 0.f;
        #pragma unroll
        for (int j = 0; j < 4; j++) acc[i][j] = 0.f;
    }

    for (int j = qt; j < NT; j++) {
        __syncthreads();    // Qt ready (iter 1) / previous PV done
        {   // load full K tile (transposed) and V tile: 16 floats each per thread
            const float* Kg = g_k + ((size_t)bh * S + j * 64) * A;
            const float* Vg = g_v + ((size_t)bh * S + j * 64) * A;
            int r = tid >> 2;
            #pragma unroll
            for (int cc = 0; cc < 4; cc++) {
                int c = (tid & 3) * 4 + cc * 16;
                float4 kv = *(const float4*)(Kg + (size_t)r * A + c);
                KtPs[(c + 0) * 64 + r] = kv.x;
                KtPs[(c + 1) * 64 + r] = kv.y;
                KtPs[(c + 2) * 64 + r] = kv.z;
                KtPs[(c + 3) * 64 + r] = kv.w;
                *(float4*)&Vs[r * 64 + c] = *(const float4*)(Vg + (size_t)r * A + c);
            }
        }
        __syncthreads();

        // scores: sc[i][jj] = q_row(ty*4+i) . k_row(tx*4+jj)
        float sc[4][4];
        #pragma unroll
        for (int i = 0; i < 4; i++)
            #pragma unroll
            for (int jj = 0; jj < 4; jj++) sc[i][jj] = 0.f;

        #pragma unroll 16
        for (int kk = 0; kk < 64; kk++) {
            float4 qa = *(const float4*)&Qt[kk * 64 + ty * 4];
            float4 kb = *(const float4*)&KtPs[kk * 64 + tx * 4];
            float av[4] = {qa.x, qa.y, qa.z, qa.w};
            float bv4[4] = {kb.x, kb.y, kb.z, kb.w};
            #pragma unroll
            for (int i = 0; i < 4; i++)
                #pragma unroll
                for (int jj = 0; jj < 4; jj++)
                    sc[i][jj] = fmaf(av[i], bv4[jj], sc[i][jj]);
        }
        __syncthreads();    // everyone done reading Kt before P overwrites it

        // scale + mask (only the diagonal tile can have kg <= qg)
        #pragma unroll
        for (int i = 0; i < 4; i++) {
            int qg = s0 + ty * 4 + i;
            #pragma unroll
            for (int jj = 0; jj < 4; jj++) {
                int kg = j * 64 + tx * 4 + jj;
                float v = sc[i][jj] * 0.125f;
                sc[i][jj] = (kg <= qg) ? -1e9f : v;
            }
        }

        // online softmax (row groups = 16-lane half-warps sharing ty)
        #pragma unroll
        for (int i = 0; i < 4; i++) {
            float m = fmaxf(fmaxf(sc[i][0], sc[i][1]), fmaxf(sc[i][2], sc[i][3]));
            #pragma unroll
            for (int o = 8; o >= 1; o >>= 1)
                m = fmaxf(m, __shfl_xor_sync(0xffffffffu, m, o));
            float m_new = fmaxf(m_run[i], m);
            float scale = __expf(m_run[i] - m_new);
            float ps[4], lsum = 0.f;
            #pragma unroll
            for (int jj = 0; jj < 4; jj++) { ps[jj] = __expf(sc[i][jj] - m_new); lsum += ps[jj]; }
            #pragma unroll
            for (int o = 8; o >= 1; o >>= 1)
                lsum += __shfl_xor_sync(0xffffffffu, lsum, o);
            l_run[i] = l_run[i] * scale + lsum;
            m_run[i] = m_new;
            #pragma unroll
            for (int jj = 0; jj < 4; jj++) acc[i][jj] *= scale;
            #pragma unroll
            for (int jj = 0; jj < 4; jj++)
                KtPs[(ty * 4 + i) * 64 + tx * 4 + jj] = ps[jj];   // P[row][key]
        }
        __syncthreads();

        // acc += P @ V   (dims d = tx*4+jj)
        #pragma unroll
        for (int kk = 0; kk < 64; kk += 4) {
            float pv[4][4];
            #pragma unroll
            for (int i = 0; i < 4; i++) {
                float4 p4 = *(const float4*)&KtPs[(ty * 4 + i) * 64 + kk];
                pv[i][0] = p4.x; pv[i][1] = p4.y; pv[i][2] = p4.z; pv[i][3] = p4.w;
            }
            #pragma unroll
            for (int t = 0; t < 4; t++) {
                float4 vb = *(const float4*)&Vs[(kk + t) * 64 + tx * 4];
                #pragma unroll
                for (int i = 0; i < 4; i++) {
                    acc[i][0] = fmaf(pv[i][t], vb.x, acc[i][0]);
                    acc[i][1] = fmaf(pv[i][t], vb.y, acc[i][1]);
                    acc[i][2] = fmaf(pv[i][t], vb.z, acc[i][2]);
                    acc[i][3] = fmaf(pv[i][t], vb.w, acc[i][3]);
                }
            }
        }
    }

    // normalize + write to g_att [b][s][h*64 + d]
    const int b = bh >> 3, h = bh & 7;
    #pragma unroll
    for (int i = 0; i < 4; i++) {
        float inv = 1.0f / l_run[i];
        int s = s0 + ty * 4 + i;
        #pragma unroll
        for (int jj = 0; jj < 4; jj++) {
            int d = tx * 4 + jj;
            g_att[((size_t)(b * S + s)) * (H * A) + h * A + d] = acc[i][jj] * inv;
        }
    }
}

// ---------------------------------------------------------------------------
// Row S-1 is entirely masked -> reference softmax is uniform 1/S -> mean(V).
// grid = BH, block = 64 (one thread per dim)
// ---------------------------------------------------------------------------
__global__ void fixup_kernel()
{
    int bh = blockIdx.x;
    int a = threadIdx.x;
    const float* Vg = g_v + (size_t)bh * S * A;
    float sum = 0.f;
    #pragma unroll 8
    for (int k = 0; k < S; k++) sum += Vg[(size_t)k * A + a];
    int b = bh >> 3, h = bh & 7;
    g_att[((size_t)(b * S + (S - 1))) * (H * A) + h * A + a] = sum * (1.0f / S);
}

// ---------------------------------------------------------------------------
// Output projection: out[b][s][:] = g_att[b][s][:] @ Wo + bo
// grid = (512/64, 8192/64), block = 256
// ---------------------------------------------------------------------------
__global__ __launch_bounds__(256) void outproj_kernel(
    const float* __restrict__ Wo, const float* __restrict__ bo,
    float* __restrict__ out)
{
    __shared__ float Xs[16][68];
    __shared__ float Ws[16][68];
    const int n0 = blockIdx.x * 64;
    const int m0 = blockIdx.y * 64;
    const int tid = threadIdx.x;
    const int ty = tid >> 4, tx = tid & 15;

    float acc[4][4];
    #pragma unroll
    for (int i = 0; i < 4; i++)
        #pragma unroll
        for (int j = 0; j < 4; j++) acc[i][j] = 0.f;

    for (int k0 = 0; k0 < 512; k0 += 16) {
        {
            int row = tid >> 2;
            int col = (tid & 3) * 4;
            float4 v = *(const float4*)(g_att + (size_t)(m0 + row) * 512 + k0 + col);
            Xs[col + 0][row] = v.x; Xs[col + 1][row] = v.y;
            Xs[col + 2][row] = v.z; Xs[col + 3][row] = v.w;
        }
        {
            int row = tid >> 4;
            int col = (tid & 15) * 4;
            *(float4*)&Ws[row][col] = *(const float4*)(Wo + (size_t)(k0 + row) * 512 + n0 + col);
        }
        __syncthreads();
        #pragma unroll
        for (int kk = 0; kk < 16; kk++) {
            float4 a4 = *(const float4*)&Xs[kk][ty * 4];
            float4 b4 = *(const float4*)&Ws[kk][tx * 4];
            float av[4] = {a4.x, a4.y, a4.z, a4.w};
            float bv4[4] = {b4.x, b4.y, b4.z, b4.w};
            #pragma unroll
            for (int i = 0; i < 4; i++)
                #pragma unroll
                for (int j = 0; j < 4; j++)
                    acc[i][j] = fmaf(av[i], bv4[j], acc[i][j]);
        }
        __syncthreads();
    }
    #pragma unroll
    for (int i = 0; i < 4; i++) {
        int m = m0 + ty * 4 + i;
        #pragma unroll
        for (int j = 0; j < 4; j++) {
            int n = n0 + tx * 4 + j;
            out[(size_t)m * 512 + n] = acc[i][j] + bo[n];
        }
    }
}

// ---------------------------------------------------------------------------
extern "C" void kernel_launch(void* const* d_in, const int* in_sizes, int n_in,
                              void* d_out, int out_size)
{
    (void)in_sizes; (void)n_in; (void)out_size;
    const float* query = (const float*)d_in[0];
    const float* key   = (const float*)d_in[1];
    const float* value = (const float*)d_in[2];
    const float* Wq    = (const float*)d_in[3];
    const float* bq    = (const float*)d_in[4];
    const float* Wk    = (const float*)d_in[5];
    const float* bk    = (const float*)d_in[6];
    const float* Wv    = (const float*)d_in[7];
    const float* bv    = (const float*)d_in[8];
    const float* Wo    = (const float*)d_in[9];
    const float* bo    = (const float*)d_in[10];
    float* out = (float*)d_out;

    proj_kernel<<<dim3(NT, BH, 3), 256>>>(query, key, value,
                                          Wq, bq, Wk, bk, Wv, bv);
    attn_kernel<<<dim3(NT, BH), 256>>>();
    fixup_kernel<<<BH, 64>>>();
    outproj_kernel<<<dim3(512 / 64, (B * S) / 64), 256>>>(Wo, bo, out);
}

// round 5
// speedup vs baseline: 1.2743x; 1.2743x over previous
#include <cuda_runtime.h>
#include <cstdint>

// Problem constants
#define B 4
#define S 2048
#define D 512
#define H 8
#define A 64
#define BH (B*H)
#define NT (S/64)
#define NROW (B*S)                 // 8192 rows
#define NX ((size_t)NROW * D)      // elements per [8192,512] matrix

// ---------------------------------------------------------------------------
// Device-global scratch (no allocations allowed)
// ---------------------------------------------------------------------------
__device__ float g_wt[(size_t)4 * D * D];  // transposed weights [mat][n=512][k=512]
__device__ float g_q[NX];                  // projected Q/K/V, layout [b*S+s][h*64+a]
__device__ float g_k[NX];
__device__ float g_v[NX];
__device__ float g_att[NX];                // attention output [b*S+s][h*64+a]

// ---------------------------------------------------------------------------
// tf32 mma.sync helpers (baseline PTX, compiles for plain sm_103 target)
// ---------------------------------------------------------------------------
__device__ __forceinline__ uint32_t f2tf32(float f) {
    uint32_t r;
    asm("cvt.rna.tf32.f32 %0, %1;" : "=r"(r) : "f"(f));
    return r;
}
__device__ __forceinline__ void mma_tf32(float* c, const uint32_t* a,
                                         uint32_t b0, uint32_t b1) {
    asm volatile(
        "mma.sync.aligned.m16n8k8.row.col.f32.tf32.tf32.f32 "
        "{%0,%1,%2,%3}, {%4,%5,%6,%7}, {%8,%9}, {%0,%1,%2,%3};"
        : "+f"(c[0]), "+f"(c[1]), "+f"(c[2]), "+f"(c[3])
        : "r"(a[0]), "r"(a[1]), "r"(a[2]), "r"(a[3]), "r"(b0), "r"(b1));
}

// ---------------------------------------------------------------------------
// Weight transpose into [n=512][k=512] fp32.
// qkv (is_o=0): src [H][D][A], wt[n][k] = src[n>>6][k][n&63]
// o   (is_o=1): src [512][512], wt[n][k] = src[k][n]
// ---------------------------------------------------------------------------
__global__ __launch_bounds__(256) void convert_w_kernel(
    const float* __restrict__ src, int mat, int is_o)
{
    int idx = blockIdx.x * 256 + threadIdx.x;   // n*512 + k
    int n = idx >> 9, k = idx & 511;
    float w = is_o ? src[(size_t)k * 512 + n]
                   : src[(size_t)(n >> 6) * (D * A) + (size_t)k * A + (n & 63)];
    g_wt[(size_t)mat * (D * D) + idx] = w;
}

// ---------------------------------------------------------------------------
// tf32 tensor GEMM body: C[8192,512] = A[8192,512] @ Wt[512,512]^T + bias
// CTA tile 128x128, 8 warps (4x2), warp tile 32x64, K-chunks of 32.
// ---------------------------------------------------------------------------
__device__ __forceinline__ void gemm_body(
    const float* __restrict__ Ag, const float* __restrict__ Wt,
    const float* __restrict__ bias, float* __restrict__ Cout,
    int m0, int n0)
{
    __shared__ float As[128][36];   // [m][k], pad 4 -> conflict-free frag loads
    __shared__ float Bs[128][36];   // [n][k]

    const int tid = threadIdx.x;
    const int lane = tid & 31;
    const int wid = tid >> 5;
    const int wm = wid >> 1;        // 0..3
    const int wn = wid & 1;         // 0..1

    float acc[2][8][4];
    #pragma unroll
    for (int mf = 0; mf < 2; mf++)
        #pragma unroll
        for (int nf = 0; nf < 8; nf++)
            #pragma unroll
            for (int i = 0; i < 4; i++) acc[mf][nf][i] = 0.f;

    for (int kc0 = 0; kc0 < 512; kc0 += 32) {
        if (kc0) __syncthreads();
        #pragma unroll
        for (int i = tid; i < 1024; i += 256) {
            int r = i >> 3, c = (i & 7) << 2;
            *(float4*)&As[r][c] = *(const float4*)(Ag + (size_t)(m0 + r) * 512 + kc0 + c);
            *(float4*)&Bs[r][c] = *(const float4*)(Wt + (size_t)(n0 + r) * 512 + kc0 + c);
        }
        __syncthreads();

        #pragma unroll
        for (int ks = 0; ks < 4; ks++) {
            const int kb = ks * 8;
            uint32_t af[2][4];
            #pragma unroll
            for (int mf = 0; mf < 2; mf++) {
                int r = wm * 32 + mf * 16 + (lane >> 2);
                int c = kb + (lane & 3);
                af[mf][0] = f2tf32(As[r][c]);
                af[mf][1] = f2tf32(As[r + 8][c]);
                af[mf][2] = f2tf32(As[r][c + 4]);
                af[mf][3] = f2tf32(As[r + 8][c + 4]);
            }
            #pragma unroll
            for (int nf = 0; nf < 8; nf++) {
                int rn = wn * 64 + nf * 8 + (lane >> 2);
                int ck = kb + (lane & 3);
                uint32_t b0 = f2tf32(Bs[rn][ck]);
                uint32_t b1 = f2tf32(Bs[rn][ck + 4]);
                mma_tf32(acc[0][nf], af[0], b0, b1);
                mma_tf32(acc[1][nf], af[1], b0, b1);
            }
        }
    }

    // epilogue
    #pragma unroll
    for (int mf = 0; mf < 2; mf++) {
        int row = m0 + wm * 32 + mf * 16 + (lane >> 2);
        #pragma unroll
        for (int nf = 0; nf < 8; nf++) {
            int col = n0 + wn * 64 + nf * 8 + ((lane & 3) << 1);
            float2 v0 = make_float2(acc[mf][nf][0] + bias[col],
                                    acc[mf][nf][1] + bias[col + 1]);
            float2 v1 = make_float2(acc[mf][nf][2] + bias[col],
                                    acc[mf][nf][3] + bias[col + 1]);
            *(float2*)(Cout + (size_t)row * 512 + col) = v0;
            *(float2*)(Cout + (size_t)(row + 8) * 512 + col) = v1;
        }
    }
}

// QKV projections: grid (64, 4, 3)
__global__ __launch_bounds__(256) void gemm_qkv_kernel(
    const float* __restrict__ q, const float* __restrict__ k,
    const float* __restrict__ v,
    const float* __restrict__ bq, const float* __restrict__ bk,
    const float* __restrict__ bv)
{
    const int z = blockIdx.z;
    const float* Ag = (z == 0) ? q : (z == 1) ? k : v;
    const float* bias = (z == 0) ? bq : (z == 1) ? bk : bv;
    float* Cout = (z == 0) ? g_q : (z == 1) ? g_k : g_v;
    gemm_body(Ag, g_wt + (size_t)z * (D * D), bias, Cout,
              blockIdx.x * 128, blockIdx.y * 128);
}

// Output projection: grid (64, 4)
__global__ __launch_bounds__(256) void gemm_o_kernel(
    const float* __restrict__ bo, float* __restrict__ out)
{
    gemm_body(g_att, g_wt + (size_t)3 * (D * D), bo, out,
              blockIdx.x * 128, blockIdx.y * 128);
}

// ---------------------------------------------------------------------------
// Flash-style attention (fp32 SIMT), mask keeps keys kg > qg.
// QKV layout: [b*S+s][h*64+a] (row stride 512).
// grid = (NT, BH), block = 256 (16x16), 4x4 micro-tiles
// ---------------------------------------------------------------------------
__global__ __launch_bounds__(256) void attn_kernel()
{
    __shared__ float Qt[64 * 64];    // [dim][qrow]
    __shared__ float KtPs[64 * 64];  // phase 1: Kt [dim][key]; phase 2: P [qrow][key]
    __shared__ float Vs[64 * 64];    // [key][dim]

    const int qt = blockIdx.x;
    const int bh = blockIdx.y;
    const int b = bh >> 3, h = bh & 7;
    const int s0 = qt * 64;
    const int tid = threadIdx.x;
    const int ty = tid >> 4, tx = tid & 15;
    const int hoff = h * 64;

    {   // load Q tile (64x64) transposed
        const float* Qg = g_q + ((size_t)(b * S + s0)) * 512 + hoff;
        int r = tid >> 2;
        #pragma unroll
        for (int cc = 0; cc < 4; cc++) {
            int c = (tid & 3) * 4 + cc * 16;
            float4 v = *(const float4*)(Qg + (size_t)r * 512 + c);
            Qt[(c + 0) * 64 + r] = v.x;
            Qt[(c + 1) * 64 + r] = v.y;
            Qt[(c + 2) * 64 + r] = v.z;
            Qt[(c + 3) * 64 + r] = v.w;
        }
    }

    float m_run[4], l_run[4], acc[4][4];
    #pragma unroll
    for (int i = 0; i < 4; i++) {
        m_run[i] = -1e9f; l_run[i] = 0.f;
        #pragma unroll
        for (int j = 0; j < 4; j++) acc[i][j] = 0.f;
    }

    for (int j = qt; j < NT; j++) {
        __syncthreads();
        {   // load K (transposed) and V tiles
            const float* Kg = g_k + ((size_t)(b * S + j * 64)) * 512 + hoff;
            const float* Vg = g_v + ((size_t)(b * S + j * 64)) * 512 + hoff;
            int r = tid >> 2;
            #pragma unroll
            for (int cc = 0; cc < 4; cc++) {
                int c = (tid & 3) * 4 + cc * 16;
                float4 kv = *(const float4*)(Kg + (size_t)r * 512 + c);
                KtPs[(c + 0) * 64 + r] = kv.x;
                KtPs[(c + 1) * 64 + r] = kv.y;
                KtPs[(c + 2) * 64 + r] = kv.z;
                KtPs[(c + 3) * 64 + r] = kv.w;
                *(float4*)&Vs[r * 64 + c] = *(const float4*)(Vg + (size_t)r * 512 + c);
            }
        }
        __syncthreads();

        float sc[4][4];
        #pragma unroll
        for (int i = 0; i < 4; i++)
            #pragma unroll
            for (int jj = 0; jj < 4; jj++) sc[i][jj] = 0.f;

        #pragma unroll 16
        for (int kk = 0; kk < 64; kk++) {
            float4 qa = *(const float4*)&Qt[kk * 64 + ty * 4];
            float4 kb = *(const float4*)&KtPs[kk * 64 + tx * 4];
            float av[4] = {qa.x, qa.y, qa.z, qa.w};
            float bv4[4] = {kb.x, kb.y, kb.z, kb.w};
            #pragma unroll
            for (int i = 0; i < 4; i++)
                #pragma unroll
                for (int jj = 0; jj < 4; jj++)
                    sc[i][jj] = fmaf(av[i], bv4[jj], sc[i][jj]);
        }
        __syncthreads();

        #pragma unroll
        for (int i = 0; i < 4; i++) {
            int qg = s0 + ty * 4 + i;
            #pragma unroll
            for (int jj = 0; jj < 4; jj++) {
                int kg = j * 64 + tx * 4 + jj;
                float v = sc[i][jj] * 0.125f;
                sc[i][jj] = (kg <= qg) ? -1e9f : v;
            }
        }

        #pragma unroll
        for (int i = 0; i < 4; i++) {
            float m = fmaxf(fmaxf(sc[i][0], sc[i][1]), fmaxf(sc[i][2], sc[i][3]));
            #pragma unroll
            for (int o = 8; o >= 1; o >>= 1)
                m = fmaxf(m, __shfl_xor_sync(0xffffffffu, m, o));
            float m_new = fmaxf(m_run[i], m);
            float scale = __expf(m_run[i] - m_new);
            float ps[4], lsum = 0.f;
            #pragma unroll
            for (int jj = 0; jj < 4; jj++) { ps[jj] = __expf(sc[i][jj] - m_new); lsum += ps[jj]; }
            #pragma unroll
            for (int o = 8; o >= 1; o >>= 1)
                lsum += __shfl_xor_sync(0xffffffffu, lsum, o);
            l_run[i] = l_run[i] * scale + lsum;
            m_run[i] = m_new;
            #pragma unroll
            for (int jj = 0; jj < 4; jj++) acc[i][jj] *= scale;
            #pragma unroll
            for (int jj = 0; jj < 4; jj++)
                KtPs[(ty * 4 + i) * 64 + tx * 4 + jj] = ps[jj];
        }
        __syncthreads();

        #pragma unroll
        for (int kk = 0; kk < 64; kk += 4) {
            float pv[4][4];
            #pragma unroll
            for (int i = 0; i < 4; i++) {
                float4 p4 = *(const float4*)&KtPs[(ty * 4 + i) * 64 + kk];
                pv[i][0] = p4.x; pv[i][1] = p4.y; pv[i][2] = p4.z; pv[i][3] = p4.w;
            }
            #pragma unroll
            for (int t = 0; t < 4; t++) {
                float4 vb = *(const float4*)&Vs[(kk + t) * 64 + tx * 4];
                #pragma unroll
                for (int i = 0; i < 4; i++) {
                    acc[i][0] = fmaf(pv[i][t], vb.x, acc[i][0]);
                    acc[i][1] = fmaf(pv[i][t], vb.y, acc[i][1]);
                    acc[i][2] = fmaf(pv[i][t], vb.z, acc[i][2]);
                    acc[i][3] = fmaf(pv[i][t], vb.w, acc[i][3]);
                }
            }
        }
    }

    // normalize + write fp32 to g_att
    #pragma unroll
    for (int i = 0; i < 4; i++) {
        float inv = 1.0f / l_run[i];
        size_t base = ((size_t)(b * S + s0 + ty * 4 + i)) * 512 + hoff;
        #pragma unroll
        for (int jj = 0; jj < 4; jj++)
            g_att[base + tx * 4 + jj] = acc[i][jj] * inv;
    }
}

// ---------------------------------------------------------------------------
// Row S-1 fully masked -> uniform softmax -> mean(V)
// ---------------------------------------------------------------------------
__global__ void fixup_kernel()
{
    int bh = blockIdx.x;
    int a = threadIdx.x;
    int b = bh >> 3, h = bh & 7;
    const float* Vg = g_v + (size_t)(b * S) * 512 + h * 64 + a;
    float sum = 0.f;
    #pragma unroll 8
    for (int k = 0; k < S; k++) sum += Vg[(size_t)k * 512];
    g_att[((size_t)(b * S + (S - 1))) * 512 + h * 64 + a] = sum * (1.0f / S);
}

// ---------------------------------------------------------------------------
extern "C" void kernel_launch(void* const* d_in, const int* in_sizes, int n_in,
                              void* d_out, int out_size)
{
    (void)in_sizes; (void)n_in; (void)out_size;
    const float* query = (const float*)d_in[0];
    const float* key   = (const float*)d_in[1];
    const float* value = (const float*)d_in[2];
    const float* Wq    = (const float*)d_in[3];
    const float* bq    = (const float*)d_in[4];
    const float* Wk    = (const float*)d_in[5];
    const float* bk    = (const float*)d_in[6];
    const float* Wv    = (const float*)d_in[7];
    const float* bv    = (const float*)d_in[8];
    const float* Wo    = (const float*)d_in[9];
    const float* bo    = (const float*)d_in[10];
    float* out = (float*)d_out;

    convert_w_kernel<<<(D * D) / 256, 256>>>(Wq, 0, 0);
    convert_w_kernel<<<(D * D) / 256, 256>>>(Wk, 1, 0);
    convert_w_kernel<<<(D * D) / 256, 256>>>(Wv, 2, 0);
    convert_w_kernel<<<(D * D) / 256, 256>>>(Wo, 3, 1);

    gemm_qkv_kernel<<<dim3(NROW / 128, 4, 3), 256>>>(query, key, value, bq, bk, bv);

    attn_kernel<<<dim3(NT, BH), 256>>>();
    fixup_kernel<<<BH, 64>>>();

    gemm_o_kernel<<<dim3(NROW / 128, 4), 256>>>(bo, out);
}

// round 7
// speedup vs baseline: 2.5215x; 1.9787x over previous
#include <cuda_runtime.h>
#include <cstdint>

// Problem constants
#define B 4
#define S 2048
#define D 512
#define H 8
#define A 64
#define BH (B*H)
#define NT (S/64)
#define NROW (B*S)                 // 8192 rows
#define NX ((size_t)NROW * D)

// ---------------------------------------------------------------------------
// Device-global scratch (no allocations allowed)
// ---------------------------------------------------------------------------
__device__ float g_wt[(size_t)4 * D * D];  // transposed weights [mat][n=512][k=512], tf32-rounded
__device__ float g_q[NX];                  // projected Q/K/V [b*S+s][h*64+a], tf32-rounded
__device__ float g_k[NX];
__device__ float g_v[NX];
__device__ float g_att[NX];                // attention output [b*S+s][h*64+a], fp32

// ---------------------------------------------------------------------------
// PTX helpers (baseline PTX only: mma.sync + cp.async, safe for sm_103 target)
// ---------------------------------------------------------------------------
__device__ __forceinline__ uint32_t f2tf32(float f) {
    uint32_t r;
    asm("cvt.rna.tf32.f32 %0, %1;" : "=r"(r) : "f"(f));
    return r;
}
__device__ __forceinline__ void mma_tf32(float* c, const uint32_t* a,
                                         uint32_t b0, uint32_t b1) {
    asm volatile(
        "mma.sync.aligned.m16n8k8.row.col.f32.tf32.tf32.f32 "
        "{%0,%1,%2,%3}, {%4,%5,%6,%7}, {%8,%9}, {%0,%1,%2,%3};"
        : "+f"(c[0]), "+f"(c[1]), "+f"(c[2]), "+f"(c[3])
        : "r"(a[0]), "r"(a[1]), "r"(a[2]), "r"(a[3]), "r"(b0), "r"(b1));
}
__device__ __forceinline__ uint32_t smem_u32(const void* p) {
    uint32_t a;
    asm("{ .reg .u64 t; cvta.to.shared.u64 t, %1; cvt.u32.u64 %0, t; }" : "=r"(a) : "l"(p));
    return a;
}
__device__ __forceinline__ void cp16(uint32_t dst, const void* src) {
    asm volatile("cp.async.cg.shared.global [%0], [%1], 16;" :: "r"(dst), "l"(src));
}
#define CP_COMMIT() asm volatile("cp.async.commit_group;" ::: "memory")
#define CP_WAIT1()  asm volatile("cp.async.wait_group 1;" ::: "memory")
#define CP_WAIT0()  asm volatile("cp.async.wait_group 0;" ::: "memory")

// ---------------------------------------------------------------------------
// Weight transpose (fused, one launch): wt[n][k], tf32-rounded.
// qkv (mat<3): src [H][D][A]: wt[n][k] = src[n>>6][k][n&63]
// o   (mat=3): src [512][512]: wt[n][k] = src[k][n]
// grid (1024, 4)
// ---------------------------------------------------------------------------
__global__ __launch_bounds__(256) void convert_w_kernel(
    const float* __restrict__ Wq, const float* __restrict__ Wk,
    const float* __restrict__ Wv, const float* __restrict__ Wo)
{
    const int mat = blockIdx.y;
    const float* src = (mat == 0) ? Wq : (mat == 1) ? Wk : (mat == 2) ? Wv : Wo;
    int idx = blockIdx.x * 256 + threadIdx.x;   // n*512 + k
    int n = idx >> 9, k = idx & 511;
    float w = (mat == 3) ? src[(size_t)k * 512 + n]
                         : src[(size_t)(n >> 6) * (D * A) + (size_t)k * A + (n & 63)];
    g_wt[(size_t)mat * (D * D) + idx] = __uint_as_float(f2tf32(w));
}

// ---------------------------------------------------------------------------
// tf32 GEMM: C[8192,512] = A[8192,512] @ Wt[512,512]^T + bias
// CTA tile 128x128, 8 warps (4x2), warp tile 32x64, K-chunks 32,
// 2-stage cp.async pipeline. Pad 44 (16B-aligned + conflict-free).
// ---------------------------------------------------------------------------
#define GP 44
#define GSEG (128*GP)          // floats per tile array
#define GSM_BYTES (4*GSEG*4)   // 90112 B

__device__ __forceinline__ void gemm_load_stage(
    uint32_t smb, const float* __restrict__ Ag, const float* __restrict__ Wt,
    int m0, int n0, int kc0, int st)
{
    const int tid = threadIdx.x;
    const uint32_t abase = smb + (uint32_t)(st * 2 * GSEG) * 4;
    const uint32_t bbase = abase + (uint32_t)GSEG * 4;
    #pragma unroll
    for (int i = 0; i < 4; i++) {
        int idx = tid + i * 256;          // 0..1023
        int r = idx >> 3, c4 = (idx & 7) * 4;
        cp16(abase + (uint32_t)(r * GP + c4) * 4, Ag + (size_t)(m0 + r) * 512 + kc0 + c4);
        cp16(bbase + (uint32_t)(r * GP + c4) * 4, Wt + (size_t)(n0 + r) * 512 + kc0 + c4);
    }
}

__device__ __forceinline__ void gemm_body(
    const float* __restrict__ Ag, const float* __restrict__ Wt,
    const float* __restrict__ bias, float* __restrict__ Cout,
    int m0, int n0, int round_out)
{
    extern __shared__ float sm[];
    const uint32_t smb = smem_u32(sm);
    const int tid = threadIdx.x;
    const int lane = tid & 31;
    const int wid = tid >> 5;
    const int wm = wid >> 1;        // 0..3
    const int wn = wid & 1;         // 0..1
    const int g = lane >> 2, t = lane & 3;

    float acc[2][8][4];
    #pragma unroll
    for (int mf = 0; mf < 2; mf++)
        #pragma unroll
        for (int nf = 0; nf < 8; nf++)
            #pragma unroll
            for (int i = 0; i < 4; i++) acc[mf][nf][i] = 0.f;

    gemm_load_stage(smb, Ag, Wt, m0, n0, 0, 0);
    CP_COMMIT();

    for (int kc = 0; kc < 16; kc++) {
        if (kc + 1 < 16) {
            gemm_load_stage(smb, Ag, Wt, m0, n0, (kc + 1) * 32, (kc + 1) & 1);
            CP_COMMIT();
            CP_WAIT1();
        } else {
            CP_WAIT0();
        }
        __syncthreads();

        const float* As = sm + (kc & 1) * 2 * GSEG;
        const float* Bs = As + GSEG;

        #pragma unroll
        for (int ks = 0; ks < 4; ks++) {
            const int kb = ks * 8;
            uint32_t af[2][4];
            #pragma unroll
            for (int mf = 0; mf < 2; mf++) {
                int r = wm * 32 + mf * 16 + g;
                int c = kb + t;
                af[mf][0] = f2tf32(As[r * GP + c]);
                af[mf][1] = f2tf32(As[(r + 8) * GP + c]);
                af[mf][2] = f2tf32(As[r * GP + c + 4]);
                af[mf][3] = f2tf32(As[(r + 8) * GP + c + 4]);
            }
            #pragma unroll
            for (int nf = 0; nf < 8; nf++) {
                int rn = wn * 64 + nf * 8 + g;
                int ck = kb + t;
                uint32_t b0 = __float_as_uint(Bs[rn * GP + ck]);      // pre-rounded tf32
                uint32_t b1 = __float_as_uint(Bs[rn * GP + ck + 4]);
                mma_tf32(acc[0][nf], af[0], b0, b1);
                mma_tf32(acc[1][nf], af[1], b0, b1);
            }
        }
        __syncthreads();
    }

    // epilogue (optionally tf32-round outputs feeding the attention kernel)
    #pragma unroll
    for (int mf = 0; mf < 2; mf++) {
        int row = m0 + wm * 32 + mf * 16 + g;
        #pragma unroll
        for (int nf = 0; nf < 8; nf++) {
            int col = n0 + wn * 64 + nf * 8 + t * 2;
            float x0 = acc[mf][nf][0] + bias[col];
            float x1 = acc[mf][nf][1] + bias[col + 1];
            float x2 = acc[mf][nf][2] + bias[col];
            float x3 = acc[mf][nf][3] + bias[col + 1];
            if (round_out) {
                x0 = __uint_as_float(f2tf32(x0)); x1 = __uint_as_float(f2tf32(x1));
                x2 = __uint_as_float(f2tf32(x2)); x3 = __uint_as_float(f2tf32(x3));
            }
            *(float2*)(Cout + (size_t)row * 512 + col) = make_float2(x0, x1);
            *(float2*)(Cout + (size_t)(row + 8) * 512 + col) = make_float2(x2, x3);
        }
    }
}

// QKV projections: grid (64, 4, 3)
__global__ __launch_bounds__(256) void gemm_qkv_kernel(
    const float* __restrict__ q, const float* __restrict__ k,
    const float* __restrict__ v,
    const float* __restrict__ bq, const float* __restrict__ bk,
    const float* __restrict__ bv)
{
    const int z = blockIdx.z;
    const float* Ag = (z == 0) ? q : (z == 1) ? k : v;
    const float* bias = (z == 0) ? bq : (z == 1) ? bk : bv;
    float* Cout = (z == 0) ? g_q : (z == 1) ? g_k : g_v;
    gemm_body(Ag, g_wt + (size_t)z * (D * D), bias, Cout,
              blockIdx.x * 128, blockIdx.y * 128, 1);
}

// Output projection: grid (64, 4)
__global__ __launch_bounds__(256) void gemm_o_kernel(
    const float* __restrict__ bo, float* __restrict__ out)
{
    gemm_body(g_att, g_wt + (size_t)3 * (D * D), bo, out,
              blockIdx.x * 128, blockIdx.y * 128, 0);
}

// ---------------------------------------------------------------------------
// Tensor-core flash attention (tf32 mma), mask keeps keys kg > qg.
// grid (NT, BH), block 128 (4 warps). Warp w owns query rows [16w, 16w+16).
// K/V tiles double-buffered via cp.async. Row S-1 fixed by fixup_kernel.
// smem float layout: Qs | Ps | K0 | V0 | K1 | V1, each 64x68.
// ---------------------------------------------------------------------------
#define AP 68
#define ASEG (64*AP)             // 4352 floats
#define ASM_BYTES (6*ASEG*4)     // 104448 B

__global__ __launch_bounds__(128) void attn_kernel()
{
    extern __shared__ float sm[];
    const uint32_t smb = smem_u32(sm);
    const int qt = blockIdx.x;
    const int bh = blockIdx.y;
    const int b = bh >> 3, h = bh & 7;
    const int s0 = qt * 64;
    const int hoff = h * 64;
    const int tid = threadIdx.x;
    const int lane = tid & 31, w = tid >> 5;
    const int g = lane >> 2, t = lane & 3;

    // prologue: Q tile + first K/V tile (group 0)
    {
        const float* Qg = g_q + ((size_t)(b * S + s0)) * 512 + hoff;
        const float* Kg = g_k + ((size_t)(b * S + qt * 64)) * 512 + hoff;
        const float* Vg = g_v + ((size_t)(b * S + qt * 64)) * 512 + hoff;
        #pragma unroll
        for (int i = 0; i < 8; i++) {
            int idx = tid + i * 128;           // 0..1023
            int r = idx >> 4, c4 = (idx & 15) * 4;
            uint32_t so = (uint32_t)(r * AP + c4) * 4;
            cp16(smb + so, Qg + (size_t)r * 512 + c4);                       // Qs
            cp16(smb + (uint32_t)(2 * ASEG) * 4 + so, Kg + (size_t)r * 512 + c4);  // K0
            cp16(smb + (uint32_t)(3 * ASEG) * 4 + so, Vg + (size_t)r * 512 + c4);  // V0
        }
        CP_COMMIT();
    }

    float m_run[2], l_run[2], oacc[8][4];
    m_run[0] = -1e30f; m_run[1] = -1e30f; l_run[0] = 0.f; l_run[1] = 0.f;
    #pragma unroll
    for (int nf = 0; nf < 8; nf++)
        #pragma unroll
        for (int i = 0; i < 4; i++) oacc[nf][i] = 0.f;

    const int row0 = s0 + w * 16 + g;
    const int row1 = row0 + 8;
    const int nTiles = NT - qt;

    for (int jj = 0; jj < nTiles; jj++) {
        const int st = jj & 1;
        if (jj + 1 < nTiles) {
            const int j1 = qt + jj + 1, st1 = (jj + 1) & 1;
            const float* Kg = g_k + ((size_t)(b * S + j1 * 64)) * 512 + hoff;
            const float* Vg = g_v + ((size_t)(b * S + j1 * 64)) * 512 + hoff;
            const uint32_t kb_ = smb + (uint32_t)((2 + 2 * st1) * ASEG) * 4;
            const uint32_t vb_ = smb + (uint32_t)((3 + 2 * st1) * ASEG) * 4;
            #pragma unroll
            for (int i = 0; i < 8; i++) {
                int idx = tid + i * 128;
                int r = idx >> 4, c4 = (idx & 15) * 4;
                uint32_t so = (uint32_t)(r * AP + c4) * 4;
                cp16(kb_ + so, Kg + (size_t)r * 512 + c4);
                cp16(vb_ + so, Vg + (size_t)r * 512 + c4);
            }
            CP_COMMIT();
            CP_WAIT1();
        } else {
            CP_WAIT0();
        }
        __syncthreads();

        const float* Qs = sm;
        float* Ps = sm + ASEG;
        const float* Ks = sm + (2 + 2 * st) * ASEG;
        const float* Vs = sm + (3 + 2 * st) * ASEG;

        // ---- scores = Q @ K^T  (all operands pre-rounded tf32) ----
        float sc[8][4];
        #pragma unroll
        for (int nf = 0; nf < 8; nf++)
            #pragma unroll
            for (int i = 0; i < 4; i++) sc[nf][i] = 0.f;

        #pragma unroll
        for (int kb = 0; kb < 64; kb += 8) {
            uint32_t af[4];
            af[0] = __float_as_uint(Qs[(w * 16 + g) * AP + kb + t]);
            af[1] = __float_as_uint(Qs[(w * 16 + g + 8) * AP + kb + t]);
            af[2] = __float_as_uint(Qs[(w * 16 + g) * AP + kb + t + 4]);
            af[3] = __float_as_uint(Qs[(w * 16 + g + 8) * AP + kb + t + 4]);
            #pragma unroll
            for (int nf = 0; nf < 8; nf++) {
                uint32_t b0 = __float_as_uint(Ks[(nf * 8 + g) * AP + kb + t]);
                uint32_t b1 = __float_as_uint(Ks[(nf * 8 + g) * AP + kb + t + 4]);
                mma_tf32(sc[nf], af, b0, b1);
            }
        }

        // ---- scale + mask (kg <= qg -> -1e9) ----
        const int j = qt + jj;
        #pragma unroll
        for (int nf = 0; nf < 8; nf++) {
            int c0 = j * 64 + nf * 8 + 2 * t;
            sc[nf][0] = (c0     <= row0) ? -1e9f : sc[nf][0] * 0.125f;
            sc[nf][1] = (c0 + 1 <= row0) ? -1e9f : sc[nf][1] * 0.125f;
            sc[nf][2] = (c0     <= row1) ? -1e9f : sc[nf][2] * 0.125f;
            sc[nf][3] = (c0 + 1 <= row1) ? -1e9f : sc[nf][3] * 0.125f;
        }

        // ---- online softmax (rows live in lane-quads) ----
        float mx0 = -1e30f, mx1 = -1e30f;
        #pragma unroll
        for (int nf = 0; nf < 8; nf++) {
            mx0 = fmaxf(mx0, fmaxf(sc[nf][0], sc[nf][1]));
            mx1 = fmaxf(mx1, fmaxf(sc[nf][2], sc[nf][3]));
        }
        mx0 = fmaxf(mx0, __shfl_xor_sync(0xffffffffu, mx0, 1));
        mx0 = fmaxf(mx0, __shfl_xor_sync(0xffffffffu, mx0, 2));
        mx1 = fmaxf(mx1, __shfl_xor_sync(0xffffffffu, mx1, 1));
        mx1 = fmaxf(mx1, __shfl_xor_sync(0xffffffffu, mx1, 2));
        float mn0 = fmaxf(m_run[0], mx0), mn1 = fmaxf(m_run[1], mx1);
        float esc0 = __expf(m_run[0] - mn0), esc1 = __expf(m_run[1] - mn1);
        float rs0 = 0.f, rs1 = 0.f;
        #pragma unroll
        for (int nf = 0; nf < 8; nf++) {
            sc[nf][0] = __expf(sc[nf][0] - mn0);
            sc[nf][1] = __expf(sc[nf][1] - mn0);
            sc[nf][2] = __expf(sc[nf][2] - mn1);
            sc[nf][3] = __expf(sc[nf][3] - mn1);
            rs0 += sc[nf][0] + sc[nf][1];
            rs1 += sc[nf][2] + sc[nf][3];
        }
        rs0 += __shfl_xor_sync(0xffffffffu, rs0, 1);
        rs0 += __shfl_xor_sync(0xffffffffu, rs0, 2);
        rs1 += __shfl_xor_sync(0xffffffffu, rs1, 1);
        rs1 += __shfl_xor_sync(0xffffffffu, rs1, 2);
        l_run[0] = l_run[0] * esc0 + rs0;
        l_run[1] = l_run[1] * esc1 + rs1;
        m_run[0] = mn0; m_run[1] = mn1;
        #pragma unroll
        for (int nf = 0; nf < 8; nf++) {
            oacc[nf][0] *= esc0; oacc[nf][1] *= esc0;
            oacc[nf][2] *= esc1; oacc[nf][3] *= esc1;
        }

        // ---- store P (tf32-rounded) to smem ----
        #pragma unroll
        for (int nf = 0; nf < 8; nf++) {
            float2 p01 = make_float2(__uint_as_float(f2tf32(sc[nf][0])),
                                     __uint_as_float(f2tf32(sc[nf][1])));
            float2 p23 = make_float2(__uint_as_float(f2tf32(sc[nf][2])),
                                     __uint_as_float(f2tf32(sc[nf][3])));
            *(float2*)&Ps[(w * 16 + g) * AP + nf * 8 + 2 * t] = p01;
            *(float2*)&Ps[(w * 16 + g + 8) * AP + nf * 8 + 2 * t] = p23;
        }
        __syncwarp();

        // ---- oacc += P @ V ----
        #pragma unroll
        for (int kb = 0; kb < 64; kb += 8) {
            uint32_t af[4];
            af[0] = __float_as_uint(Ps[(w * 16 + g) * AP + kb + t]);
            af[1] = __float_as_uint(Ps[(w * 16 + g + 8) * AP + kb + t]);
            af[2] = __float_as_uint(Ps[(w * 16 + g) * AP + kb + t + 4]);
            af[3] = __float_as_uint(Ps[(w * 16 + g + 8) * AP + kb + t + 4]);
            #pragma unroll
            for (int nf = 0; nf < 8; nf++) {
                uint32_t b0 = __float_as_uint(Vs[(kb + t) * AP + nf * 8 + g]);
                uint32_t b1 = __float_as_uint(Vs[(kb + t + 4) * AP + nf * 8 + g]);
                mma_tf32(oacc[nf], af, b0, b1);
            }
        }
        __syncthreads();   // protect K/V stage + allow safe refill
    }

    // ---- normalize + write ----
    float inv0 = 1.0f / l_run[0];
    float inv1 = 1.0f / l_run[1];
    float* O0 = g_att + ((size_t)(b * S + row0)) * 512 + hoff;
    float* O1 = g_att + ((size_t)(b * S + row1)) * 512 + hoff;
    #pragma unroll
    for (int nf = 0; nf < 8; nf++) {
        int col = nf * 8 + 2 * t;
        *(float2*)(O0 + col) = make_float2(oacc[nf][0] * inv0, oacc[nf][1] * inv0);
        *(float2*)(O1 + col) = make_float2(oacc[nf][2] * inv1, oacc[nf][3] * inv1);
    }
}

// ---------------------------------------------------------------------------
// Row S-1 fully masked -> uniform softmax -> mean(V)
// ---------------------------------------------------------------------------
__global__ void fixup_kernel()
{
    int bh = blockIdx.x;
    int a = threadIdx.x;
    int b = bh >> 3, h = bh & 7;
    const float* Vg = g_v + (size_t)(b * S) * 512 + h * 64 + a;
    float sum = 0.f;
    #pragma unroll 8
    for (int k = 0; k < S; k++) sum += Vg[(size_t)k * 512];
    g_att[((size_t)(b * S + (S - 1))) * 512 + h * 64 + a] = sum * (1.0f / S);
}

// ---------------------------------------------------------------------------
extern "C" void kernel_launch(void* const* d_in, const int* in_sizes, int n_in,
                              void* d_out, int out_size)
{
    (void)in_sizes; (void)n_in; (void)out_size;
    const float* query = (const float*)d_in[0];
    const float* key   = (const float*)d_in[1];
    const float* value = (const float*)d_in[2];
    const float* Wq    = (const float*)d_in[3];
    const float* bq    = (const float*)d_in[4];
    const float* Wk    = (const float*)d_in[5];
    const float* bk    = (const float*)d_in[6];
    const float* Wv    = (const float*)d_in[7];
    const float* bv    = (const float*)d_in[8];
    const float* Wo    = (const float*)d_in[9];
    const float* bo    = (const float*)d_in[10];
    float* out = (float*)d_out;

    // unconditional every call (idempotent; no static state per harness rules)
    cudaFuncSetAttribute(gemm_qkv_kernel, cudaFuncAttributeMaxDynamicSharedMemorySize, GSM_BYTES);
    cudaFuncSetAttribute(gemm_o_kernel,   cudaFuncAttributeMaxDynamicSharedMemorySize, GSM_BYTES);
    cudaFuncSetAttribute(attn_kernel,     cudaFuncAttributeMaxDynamicSharedMemorySize, ASM_BYTES);

    convert_w_kernel<<<dim3(1024, 4), 256>>>(Wq, Wk, Wv, Wo);

    gemm_qkv_kernel<<<dim3(NROW / 128, 4, 3), 256, GSM_BYTES>>>(query, key, value, bq, bk, bv);

    attn_kernel<<<dim3(NT, BH), 128, ASM_BYTES>>>();
    fixup_kernel<<<BH, 64>>>();

    gemm_o_kernel<<<dim3(NROW / 128, 4), 256, GSM_BYTES>>>(bo, out);
}

// round 9
// speedup vs baseline: 3.0831x; 1.2227x over previous
#include <cuda_runtime.h>
#include <cstdint>

// Problem constants
#define B 4
#define S 2048
#define D 512
#define H 8
#define A 64
#define BH (B*H)
#define NT (S/64)
#define NROW (B*S)                 // 8192 rows
#define NX ((size_t)NROW * D)

// ---------------------------------------------------------------------------
// Device-global scratch (no allocations allowed)
// ---------------------------------------------------------------------------
__device__ float g_wt[(size_t)4 * D * D];  // transposed weights [mat][n=512][k=512], tf32-rounded
__device__ float g_q[NX];                  // projected Q/K/V [b*S+s][h*64+a], tf32-rounded
__device__ float g_k[NX];
__device__ float g_v[NX];
__device__ float g_att[NX];                // attention output [b*S+s][h*64+a], fp32

// ---------------------------------------------------------------------------
// PTX helpers (baseline PTX only: mma.sync + cp.async, safe for sm_103 target)
// ---------------------------------------------------------------------------
__device__ __forceinline__ uint32_t f2tf32(float f) {
    uint32_t r;
    asm("cvt.rna.tf32.f32 %0, %1;" : "=r"(r) : "f"(f));
    return r;
}
__device__ __forceinline__ void mma_tf32(float* c, const uint32_t* a,
                                         uint32_t b0, uint32_t b1) {
    asm volatile(
        "mma.sync.aligned.m16n8k8.row.col.f32.tf32.tf32.f32 "
        "{%0,%1,%2,%3}, {%4,%5,%6,%7}, {%8,%9}, {%0,%1,%2,%3};"
        : "+f"(c[0]), "+f"(c[1]), "+f"(c[2]), "+f"(c[3])
        : "r"(a[0]), "r"(a[1]), "r"(a[2]), "r"(a[3]), "r"(b0), "r"(b1));
}
__device__ __forceinline__ uint32_t smem_u32(const void* p) {
    uint32_t a;
    asm("{ .reg .u64 t; cvta.to.shared.u64 t, %1; cvt.u32.u64 %0, t; }" : "=r"(a) : "l"(p));
    return a;
}
__device__ __forceinline__ void cp16(uint32_t dst, const void* src) {
    asm volatile("cp.async.cg.shared.global [%0], [%1], 16;" :: "r"(dst), "l"(src));
}
#define CP_COMMIT() asm volatile("cp.async.commit_group;" ::: "memory")
#define CP_WAIT1()  asm volatile("cp.async.wait_group 1;" ::: "memory")
#define CP_WAIT0()  asm volatile("cp.async.wait_group 0;" ::: "memory")

// ---------------------------------------------------------------------------
// Weight transpose (fused, one launch): wt[n][k], tf32-rounded.
// qkv (mat<3): src [H][D][A]: wt[n][k] = src[n>>6][k][n&63]
// o   (mat=3): src [512][512]: wt[n][k] = src[k][n]
// grid (1024, 4)
// ---------------------------------------------------------------------------
__global__ __launch_bounds__(256) void convert_w_kernel(
    const float* __restrict__ Wq, const float* __restrict__ Wk,
    const float* __restrict__ Wv, const float* __restrict__ Wo)
{
    const int mat = blockIdx.y;
    const float* src = (mat == 0) ? Wq : (mat == 1) ? Wk : (mat == 2) ? Wv : Wo;
    int idx = blockIdx.x * 256 + threadIdx.x;   // n*512 + k
    int n = idx >> 9, k = idx & 511;
    float w = (mat == 3) ? src[(size_t)k * 512 + n]
                         : src[(size_t)(n >> 6) * (D * A) + (size_t)k * A + (n & 63)];
    g_wt[(size_t)mat * (D * D) + idx] = __uint_as_float(f2tf32(w));
}

// ---------------------------------------------------------------------------
// tf32 GEMM: C[8192,512] = A[8192,512] @ Wt[512,512]^T + bias
// CTA tile 128x128, 8 warps (4x2), warp tile 32x64, K-chunks 32,
// 2-stage cp.async pipeline. Pad 44 (16B-aligned + conflict-free).
// ---------------------------------------------------------------------------
#define GP 44
#define GSEG (128*GP)          // floats per tile array
#define GSM_BYTES (4*GSEG*4)   // 90112 B

__device__ __forceinline__ void gemm_load_stage(
    uint32_t smb, const float* __restrict__ Ag, const float* __restrict__ Wt,
    int m0, int n0, int kc0, int st)
{
    const int tid = threadIdx.x;
    const uint32_t abase = smb + (uint32_t)(st * 2 * GSEG) * 4;
    const uint32_t bbase = abase + (uint32_t)GSEG * 4;
    #pragma unroll
    for (int i = 0; i < 4; i++) {
        int idx = tid + i * 256;          // 0..1023
        int r = idx >> 3, c4 = (idx & 7) * 4;
        cp16(abase + (uint32_t)(r * GP + c4) * 4, Ag + (size_t)(m0 + r) * 512 + kc0 + c4);
        cp16(bbase + (uint32_t)(r * GP + c4) * 4, Wt + (size_t)(n0 + r) * 512 + kc0 + c4);
    }
}

__device__ __forceinline__ void gemm_body(
    const float* __restrict__ Ag, const float* __restrict__ Wt,
    const float* __restrict__ bias, float* __restrict__ Cout,
    int m0, int n0, int round_out)
{
    extern __shared__ float sm[];
    const uint32_t smb = smem_u32(sm);
    const int tid = threadIdx.x;
    const int lane = tid & 31;
    const int wid = tid >> 5;
    const int wm = wid >> 1;        // 0..3
    const int wn = wid & 1;         // 0..1
    const int g = lane >> 2, t = lane & 3;

    float acc[2][8][4];
    #pragma unroll
    for (int mf = 0; mf < 2; mf++)
        #pragma unroll
        for (int nf = 0; nf < 8; nf++)
            #pragma unroll
            for (int i = 0; i < 4; i++) acc[mf][nf][i] = 0.f;

    gemm_load_stage(smb, Ag, Wt, m0, n0, 0, 0);
    CP_COMMIT();

    for (int kc = 0; kc < 16; kc++) {
        if (kc + 1 < 16) {
            gemm_load_stage(smb, Ag, Wt, m0, n0, (kc + 1) * 32, (kc + 1) & 1);
            CP_COMMIT();
            CP_WAIT1();
        } else {
            CP_WAIT0();
        }
        __syncthreads();

        const float* As = sm + (kc & 1) * 2 * GSEG;
        const float* Bs = As + GSEG;

        #pragma unroll
        for (int ks = 0; ks < 4; ks++) {
            const int kb = ks * 8;
            uint32_t af[2][4];
            #pragma unroll
            for (int mf = 0; mf < 2; mf++) {
                int r = wm * 32 + mf * 16 + g;
                int c = kb + t;
                af[mf][0] = f2tf32(As[r * GP + c]);
                af[mf][1] = f2tf32(As[(r + 8) * GP + c]);
                af[mf][2] = f2tf32(As[r * GP + c + 4]);
                af[mf][3] = f2tf32(As[(r + 8) * GP + c + 4]);
            }
            #pragma unroll
            for (int nf = 0; nf < 8; nf++) {
                int rn = wn * 64 + nf * 8 + g;
                int ck = kb + t;
                uint32_t b0 = __float_as_uint(Bs[rn * GP + ck]);      // pre-rounded tf32
                uint32_t b1 = __float_as_uint(Bs[rn * GP + ck + 4]);
                mma_tf32(acc[0][nf], af[0], b0, b1);
                mma_tf32(acc[1][nf], af[1], b0, b1);
            }
        }
        __syncthreads();
    }

    // epilogue (optionally tf32-round outputs feeding the attention kernel)
    #pragma unroll
    for (int mf = 0; mf < 2; mf++) {
        int row = m0 + wm * 32 + mf * 16 + g;
        #pragma unroll
        for (int nf = 0; nf < 8; nf++) {
            int col = n0 + wn * 64 + nf * 8 + t * 2;
            float x0 = acc[mf][nf][0] + bias[col];
            float x1 = acc[mf][nf][1] + bias[col + 1];
            float x2 = acc[mf][nf][2] + bias[col];
            float x3 = acc[mf][nf][3] + bias[col + 1];
            if (round_out) {
                x0 = __uint_as_float(f2tf32(x0)); x1 = __uint_as_float(f2tf32(x1));
                x2 = __uint_as_float(f2tf32(x2)); x3 = __uint_as_float(f2tf32(x3));
            }
            *(float2*)(Cout + (size_t)row * 512 + col) = make_float2(x0, x1);
            *(float2*)(Cout + (size_t)(row + 8) * 512 + col) = make_float2(x2, x3);
        }
    }
}

// QKV projections: grid (64, 4, 3)
__global__ __launch_bounds__(256) void gemm_qkv_kernel(
    const float* __restrict__ q, const float* __restrict__ k,
    const float* __restrict__ v,
    const float* __restrict__ bq, const float* __restrict__ bk,
    const float* __restrict__ bv)
{
    const int z = blockIdx.z;
    const float* Ag = (z == 0) ? q : (z == 1) ? k : v;
    const float* bias = (z == 0) ? bq : (z == 1) ? bk : bv;
    float* Cout = (z == 0) ? g_q : (z == 1) ? g_k : g_v;
    gemm_body(Ag, g_wt + (size_t)z * (D * D), bias, Cout,
              blockIdx.x * 128, blockIdx.y * 128, 1);
}

// Output projection: grid (64, 4)
__global__ __launch_bounds__(256) void gemm_o_kernel(
    const float* __restrict__ bo, float* __restrict__ out)
{
    gemm_body(g_att, g_wt + (size_t)3 * (D * D), bo, out,
              blockIdx.x * 128, blockIdx.y * 128, 0);
}

// ---------------------------------------------------------------------------
// Tensor-core flash attention (tf32 mma), mask keeps keys kg > qg.
// grid (NT, BH), block 128 (4 warps). Warp w owns query rows [16w, 16w+16).
// K/V tiles double-buffered via cp.async. Row S-1 fixed by fixup_kernel.
// smem float layout: Qs | Ps | K0 | V0 | K1 | V1, each 64x68.
// ---------------------------------------------------------------------------
#define AP 68
#define ASEG (64*AP)             // 4352 floats
#define ASM_BYTES (6*ASEG*4)     // 104448 B

__global__ __launch_bounds__(128) void attn_kernel()
{
    extern __shared__ float sm[];
    const uint32_t smb = smem_u32(sm);
    const int qt = blockIdx.x;
    const int bh = blockIdx.y;
    const int b = bh >> 3, h = bh & 7;
    const int s0 = qt * 64;
    const int hoff = h * 64;
    const int tid = threadIdx.x;
    const int lane = tid & 31, w = tid >> 5;
    const int g = lane >> 2, t = lane & 3;

    // prologue: Q tile + first K/V tile (group 0)
    {
        const float* Qg = g_q + ((size_t)(b * S + s0)) * 512 + hoff;
        const float* Kg = g_k + ((size_t)(b * S + qt * 64)) * 512 + hoff;
        const float* Vg = g_v + ((size_t)(b * S + qt * 64)) * 512 + hoff;
        #pragma unroll
        for (int i = 0; i < 8; i++) {
            int idx = tid + i * 128;           // 0..1023
            int r = idx >> 4, c4 = (idx & 15) * 4;
            uint32_t so = (uint32_t)(r * AP + c4) * 4;
            cp16(smb + so, Qg + (size_t)r * 512 + c4);                       // Qs
            cp16(smb + (uint32_t)(2 * ASEG) * 4 + so, Kg + (size_t)r * 512 + c4);  // K0
            cp16(smb + (uint32_t)(3 * ASEG) * 4 + so, Vg + (size_t)r * 512 + c4);  // V0
        }
        CP_COMMIT();
    }

    float m_run[2], l_run[2], oacc[8][4];
    m_run[0] = -1e30f; m_run[1] = -1e30f; l_run[0] = 0.f; l_run[1] = 0.f;
    #pragma unroll
    for (int nf = 0; nf < 8; nf++)
        #pragma unroll
        for (int i = 0; i < 4; i++) oacc[nf][i] = 0.f;

    const int row0 = s0 + w * 16 + g;
    const int row1 = row0 + 8;
    const int nTiles = NT - qt;

    for (int jj = 0; jj < nTiles; jj++) {
        const int st = jj & 1;
        if (jj + 1 < nTiles) {
            const int j1 = qt + jj + 1, st1 = (jj + 1) & 1;
            const float* Kg = g_k + ((size_t)(b * S + j1 * 64)) * 512 + hoff;
            const float* Vg = g_v + ((size_t)(b * S + j1 * 64)) * 512 + hoff;
            const uint32_t kb_ = smb + (uint32_t)((2 + 2 * st1) * ASEG) * 4;
            const uint32_t vb_ = smb + (uint32_t)((3 + 2 * st1) * ASEG) * 4;
            #pragma unroll
            for (int i = 0; i < 8; i++) {
                int idx = tid + i * 128;
                int r = idx >> 4, c4 = (idx & 15) * 4;
                uint32_t so = (uint32_t)(r * AP + c4) * 4;
                cp16(kb_ + so, Kg + (size_t)r * 512 + c4);
                cp16(vb_ + so, Vg + (size_t)r * 512 + c4);
            }
            CP_COMMIT();
            CP_WAIT1();
        } else {
            CP_WAIT0();
        }
        __syncthreads();

        const float* Qs = sm;
        float* Ps = sm + ASEG;
        const float* Ks = sm + (2 + 2 * st) * ASEG;
        const float* Vs = sm + (3 + 2 * st) * ASEG;

        // ---- scores = Q @ K^T  (all operands pre-rounded tf32) ----
        float sc[8][4];
        #pragma unroll
        for (int nf = 0; nf < 8; nf++)
            #pragma unroll
            for (int i = 0; i < 4; i++) sc[nf][i] = 0.f;

        #pragma unroll
        for (int kb = 0; kb < 64; kb += 8) {
            uint32_t af[4];
            af[0] = __float_as_uint(Qs[(w * 16 + g) * AP + kb + t]);
            af[1] = __float_as_uint(Qs[(w * 16 + g + 8) * AP + kb + t]);
            af[2] = __float_as_uint(Qs[(w * 16 + g) * AP + kb + t + 4]);
            af[3] = __float_as_uint(Qs[(w * 16 + g + 8) * AP + kb + t + 4]);
            #pragma unroll
            for (int nf = 0; nf < 8; nf++) {
                uint32_t b0 = __float_as_uint(Ks[(nf * 8 + g) * AP + kb + t]);
                uint32_t b1 = __float_as_uint(Ks[(nf * 8 + g) * AP + kb + t + 4]);
                mma_tf32(sc[nf], af, b0, b1);
            }
        }

        // ---- scale + mask (kg <= qg -> -1e9) ----
        const int j = qt + jj;
        #pragma unroll
        for (int nf = 0; nf < 8; nf++) {
            int c0 = j * 64 + nf * 8 + 2 * t;
            sc[nf][0] = (c0     <= row0) ? -1e9f : sc[nf][0] * 0.125f;
            sc[nf][1] = (c0 + 1 <= row0) ? -1e9f : sc[nf][1] * 0.125f;
            sc[nf][2] = (c0     <= row1) ? -1e9f : sc[nf][2] * 0.125f;
            sc[nf][3] = (c0 + 1 <= row1) ? -1e9f : sc[nf][3] * 0.125f;
        }

        // ---- online softmax (rows live in lane-quads) ----
        float mx0 = -1e30f, mx1 = -1e30f;
        #pragma unroll
        for (int nf = 0; nf < 8; nf++) {
            mx0 = fmaxf(mx0, fmaxf(sc[nf][0], sc[nf][1]));
            mx1 = fmaxf(mx1, fmaxf(sc[nf][2], sc[nf][3]));
        }
        mx0 = fmaxf(mx0, __shfl_xor_sync(0xffffffffu, mx0, 1));
        mx0 = fmaxf(mx0, __shfl_xor_sync(0xffffffffu, mx0, 2));
        mx1 = fmaxf(mx1, __shfl_xor_sync(0xffffffffu, mx1, 1));
        mx1 = fmaxf(mx1, __shfl_xor_sync(0xffffffffu, mx1, 2));
        float mn0 = fmaxf(m_run[0], mx0), mn1 = fmaxf(m_run[1], mx1);
        float esc0 = __expf(m_run[0] - mn0), esc1 = __expf(m_run[1] - mn1);
        float rs0 = 0.f, rs1 = 0.f;
        #pragma unroll
        for (int nf = 0; nf < 8; nf++) {
            sc[nf][0] = __expf(sc[nf][0] - mn0);
            sc[nf][1] = __expf(sc[nf][1] - mn0);
            sc[nf][2] = __expf(sc[nf][2] - mn1);
            sc[nf][3] = __expf(sc[nf][3] - mn1);
            rs0 += sc[nf][0] + sc[nf][1];
            rs1 += sc[nf][2] + sc[nf][3];
        }
        rs0 += __shfl_xor_sync(0xffffffffu, rs0, 1);
        rs0 += __shfl_xor_sync(0xffffffffu, rs0, 2);
        rs1 += __shfl_xor_sync(0xffffffffu, rs1, 1);
        rs1 += __shfl_xor_sync(0xffffffffu, rs1, 2);
        l_run[0] = l_run[0] * esc0 + rs0;
        l_run[1] = l_run[1] * esc1 + rs1;
        m_run[0] = mn0; m_run[1] = mn1;
        #pragma unroll
        for (int nf = 0; nf < 8; nf++) {
            oacc[nf][0] *= esc0; oacc[nf][1] *= esc0;
            oacc[nf][2] *= esc1; oacc[nf][3] *= esc1;
        }

        // ---- store P (tf32-rounded) to smem ----
        #pragma unroll
        for (int nf = 0; nf < 8; nf++) {
            float2 p01 = make_float2(__uint_as_float(f2tf32(sc[nf][0])),
                                     __uint_as_float(f2tf32(sc[nf][1])));
            float2 p23 = make_float2(__uint_as_float(f2tf32(sc[nf][2])),
                                     __uint_as_float(f2tf32(sc[nf][3])));
            *(float2*)&Ps[(w * 16 + g) * AP + nf * 8 + 2 * t] = p01;
            *(float2*)&Ps[(w * 16 + g + 8) * AP + nf * 8 + 2 * t] = p23;
        }
        __syncwarp();

        // ---- oacc += P @ V ----
        #pragma unroll
        for (int kb = 0; kb < 64; kb += 8) {
            uint32_t af[4];
            af[0] = __float_as_uint(Ps[(w * 16 + g) * AP + kb + t]);
            af[1] = __float_as_uint(Ps[(w * 16 + g + 8) * AP + kb + t]);
            af[2] = __float_as_uint(Ps[(w * 16 + g) * AP + kb + t + 4]);
            af[3] = __float_as_uint(Ps[(w * 16 + g + 8) * AP + kb + t + 4]);
            #pragma unroll
            for (int nf = 0; nf < 8; nf++) {
                uint32_t b0 = __float_as_uint(Vs[(kb + t) * AP + nf * 8 + g]);
                uint32_t b1 = __float_as_uint(Vs[(kb + t + 4) * AP + nf * 8 + g]);
                mma_tf32(oacc[nf], af, b0, b1);
            }
        }
        __syncthreads();   // protect K/V stage + allow safe refill
    }

    // ---- normalize + write ----
    float inv0 = 1.0f / l_run[0];
    float inv1 = 1.0f / l_run[1];
    float* O0 = g_att + ((size_t)(b * S + row0)) * 512 + hoff;
    float* O1 = g_att + ((size_t)(b * S + row1)) * 512 + hoff;
    #pragma unroll
    for (int nf = 0; nf < 8; nf++) {
        int col = nf * 8 + 2 * t;
        *(float2*)(O0 + col) = make_float2(oacc[nf][0] * inv0, oacc[nf][1] * inv0);
        *(float2*)(O1 + col) = make_float2(oacc[nf][2] * inv1, oacc[nf][3] * inv1);
    }
}

// ---------------------------------------------------------------------------
// Row S-1 fully masked -> uniform softmax -> mean(V).
// One block per bh, 1024 threads: 16 row-chunks x 64 columns, smem tree.
// ---------------------------------------------------------------------------
__global__ __launch_bounds__(1024) void fixup_kernel()
{
    __shared__ float red[16][64];
    const int bh = blockIdx.x;
    const int b = bh >> 3, h = bh & 7;
    const int a = threadIdx.x & 63;
    const int chunk = threadIdx.x >> 6;      // 0..15

    const float* Vg = g_v + (size_t)(b * S) * 512 + h * 64 + a;
    float sum = 0.f;
    const int s0 = chunk * 128;
    #pragma unroll 8
    for (int s = 0; s < 128; s++)
        sum += Vg[(size_t)(s0 + s) * 512];
    red[chunk][a] = sum;
    __syncthreads();

    if (chunk < 8) red[chunk][a] += red[chunk + 8][a];
    __syncthreads();
    if (chunk < 4) red[chunk][a] += red[chunk + 4][a];
    __syncthreads();
    if (chunk < 2) red[chunk][a] += red[chunk + 2][a];
    __syncthreads();
    if (chunk == 0) {
        float total = red[0][a] + red[1][a];
        g_att[((size_t)(b * S + (S - 1))) * 512 + h * 64 + a] = total * (1.0f / S);
    }
}

// ---------------------------------------------------------------------------
extern "C" void kernel_launch(void* const* d_in, const int* in_sizes, int n_in,
                              void* d_out, int out_size)
{
    (void)in_sizes; (void)n_in; (void)out_size;
    const float* query = (const float*)d_in[0];
    const float* key   = (const float*)d_in[1];
    const float* value = (const float*)d_in[2];
    const float* Wq    = (const float*)d_in[3];
    const float* bq    = (const float*)d_in[4];
    const float* Wk    = (const float*)d_in[5];
    const float* bk    = (const float*)d_in[6];
    const float* Wv    = (const float*)d_in[7];
    const float* bv    = (const float*)d_in[8];
    const float* Wo    = (const float*)d_in[9];
    const float* bo    = (const float*)d_in[10];
    float* out = (float*)d_out;

    // unconditional every call (idempotent; no static state per harness rules)
    cudaFuncSetAttribute(gemm_qkv_kernel, cudaFuncAttributeMaxDynamicSharedMemorySize, GSM_BYTES);
    cudaFuncSetAttribute(gemm_o_kernel,   cudaFuncAttributeMaxDynamicSharedMemorySize, GSM_BYTES);
    cudaFuncSetAttribute(attn_kernel,     cudaFuncAttributeMaxDynamicSharedMemorySize, ASM_BYTES);

    convert_w_kernel<<<dim3(1024, 4), 256>>>(Wq, Wk, Wv, Wo);

    gemm_qkv_kernel<<<dim3(NROW / 128, 4, 3), 256, GSM_BYTES>>>(query, key, value, bq, bk, bv);

    attn_kernel<<<dim3(NT, BH), 128, ASM_BYTES>>>();
    fixup_kernel<<<BH, 1024>>>();

    gemm_o_kernel<<<dim3(NROW / 128, 4), 256, GSM_BYTES>>>(bo, out);
}